// round 14
// baseline (speedup 1.0000x reference)
#include <cuda_runtime.h>
#include <cuda_fp16.h>
#include <cstdint>

// Problem constants (fixed shapes for this instance)
#define N_NODES 50000
#define N_EDGES 600000
#define CH      128          // IN_CH == OUT_CH == 128, HEADS == 1
#define CAP     96           // per-node bucket capacity
#define OVF_MAX 16384        // overflow edge list capacity (correctness fallback)

#define LDA 136              // padded fp16 row stride (272 B) for ldmatrix tiles

// ---------------------------------------------------------------------------
// Scratch (no cudaMalloc allowed)
// ---------------------------------------------------------------------------
__device__ __half d_xh[(size_t)N_NODES * CH];      // x in fp16
__device__ __half d_sh[(size_t)N_NODES * CH];      // aggregated features, fp16
__device__ int    d_deg[N_NODES];                  // in-degree (excl. self loop)
__device__ int    d_bucket[(size_t)N_NODES * CAP]; // per-dst source lists
__device__ int    d_is64;                          // edge_index dtype flag
__device__ int    d_ovf_cnt;
__device__ int    d_ovf[OVF_MAX * 2];
__device__ __half d_Wh[CH * LDA];                  // W^T [n][k], fp16, padded

// ---------------------------------------------------------------------------
// MMA helpers (baseline PTX, legal on plain sm_103)
// ---------------------------------------------------------------------------
__device__ __forceinline__ uint32_t smem_to_u32(const void* p) {
    uint32_t a;
    asm("{ .reg .u64 t; cvta.to.shared.u64 t, %1; cvt.u32.u64 %0, t; }"
        : "=r"(a) : "l"(p));
    return a;
}
__device__ __forceinline__ void ldsm_x4(uint32_t* r, uint32_t addr) {
    asm volatile("ldmatrix.sync.aligned.m8n8.x4.shared.b16 {%0,%1,%2,%3}, [%4];"
                 : "=r"(r[0]), "=r"(r[1]), "=r"(r[2]), "=r"(r[3]) : "r"(addr));
}
__device__ __forceinline__ void mma_fp16(float* c, const uint32_t* a,
                                         uint32_t b0, uint32_t b1) {
    asm volatile("mma.sync.aligned.m16n8k16.row.col.f32.f16.f16.f32 "
                 "{%0,%1,%2,%3}, {%4,%5,%6,%7}, {%8,%9}, {%0,%1,%2,%3};"
                 : "+f"(c[0]), "+f"(c[1]), "+f"(c[2]), "+f"(c[3])
                 : "r"(a[0]), "r"(a[1]), "r"(a[2]), "r"(a[3]), "r"(b0), "r"(b1));
}

// ---------------------------------------------------------------------------
// Prep: x -> fp16, W -> fp16 [n][k] padded, zero deg, sniff dtype. One launch.
// ---------------------------------------------------------------------------
__global__ void prep_kernel(const float* __restrict__ x,
                            const float* __restrict__ W,
                            const void* __restrict__ ei, int n_nodes) {
    int i = blockIdx.x * blockDim.x + threadIdx.x;
    int n4 = n_nodes * (CH / 4);
    if (i < n4) {
        float4 v = *(const float4*)(x + (size_t)i * 4);
        __half2 h01 = __floats2half2_rn(v.x, v.y);
        __half2 h23 = __floats2half2_rn(v.z, v.w);
        uint2 pack;
        pack.x = *(uint32_t*)&h01;
        pack.y = *(uint32_t*)&h23;
        *(uint2*)(d_xh + (size_t)i * 4) = pack;
    }
    if (i < n_nodes) d_deg[i] = 0;
    if (i < CH * LDA) {
        int n = i / LDA;
        int k = i % LDA;
        float w = (k < CH) ? W[(size_t)k * CH + n] : 0.0f;
        d_Wh[i] = __float2half_rn(w);
    }
    if (i == 0) {
        d_ovf_cnt = 0;
        const unsigned long long* p = (const unsigned long long*)ei;
        int is64 = 1;
        #pragma unroll
        for (int j = 0; j < 16; j++)
            if (p[j] >> 32) is64 = 0;
        d_is64 = is64;
    }
}

// ---------------------------------------------------------------------------
// Histogram + bucket fill (one edge per thread)
// ---------------------------------------------------------------------------
__global__ void histo_fill_kernel(const void* __restrict__ ei, int n_edges) {
    int e = blockIdx.x * blockDim.x + threadIdx.x;
    if (e >= n_edges) return;
    int src, dst;
    if (d_is64) {
        const long long* p = (const long long*)ei;
        src = (int)p[e];
        dst = (int)p[n_edges + e];
    } else {
        const int* p = (const int*)ei;
        src = p[e];
        dst = p[n_edges + e];
    }
    int pos = atomicAdd(&d_deg[dst], 1);
    if (pos < CAP) {
        d_bucket[dst * CAP + pos] = src;
    } else {
        int j = atomicAdd(&d_ovf_cnt, 1);
        if (j < OVF_MAX) { d_ovf[2 * j] = src; d_ovf[2 * j + 1] = dst; }
    }
}

// ---------------------------------------------------------------------------
// Gather (node range [node0, node1)): warp per node, fp16 rows, pairwise
// fp16 pre-add (__hadd2) then fp32 accumulate.
// ---------------------------------------------------------------------------
__device__ __forceinline__ uint2 ldcg2(const __half* p) {
    uint2 v;
    asm volatile("ld.global.cg.v2.u32 {%0,%1}, [%2];"
                 : "=r"(v.x), "=r"(v.y) : "l"(p));
    return v;
}
__device__ __forceinline__ void acc_h4(float* f, uint2 v) {
    __half2 h01 = *(__half2*)&v.x;
    __half2 h23 = *(__half2*)&v.y;
    float2 f01 = __half22float2(h01);
    float2 f23 = __half22float2(h23);
    f[0] += f01.x; f[1] += f01.y; f[2] += f23.x; f[3] += f23.y;
}
__device__ __forceinline__ void acc_pair(float* f, uint2 va, uint2 vb) {
    __half2 p01 = __hadd2(*(__half2*)&va.x, *(__half2*)&vb.x);
    __half2 p23 = __hadd2(*(__half2*)&va.y, *(__half2*)&vb.y);
    float2 f01 = __half22float2(p01);
    float2 f23 = __half22float2(p23);
    f[0] += f01.x; f[1] += f01.y; f[2] += f23.x; f[3] += f23.y;
}

__global__ __launch_bounds__(128)
void gather_kernel(int node0, int node1) {
    int node = node0 + ((blockIdx.x * blockDim.x + threadIdx.x) >> 5);
    int lane = threadIdx.x & 31;
    if (node >= node1) return;

    int deg = d_deg[node];
    int nb  = min(deg, CAP);
    const size_t rb = (size_t)node * CH + lane * 4;

    float acc[4] = {0.f, 0.f, 0.f, 0.f};
    acc_h4(acc, ldcg2(d_xh + rb));                 // self loop

    int base = node * CAP;
    for (int e0 = 0; e0 < nb; e0 += 32) {
        int idx = 0;
        if (e0 + lane < nb) idx = d_bucket[base + e0 + lane];
        int m = min(32, nb - e0);
        int t = 0;
        for (; t + 4 <= m; t += 4) {
            int s0 = __shfl_sync(0xFFFFFFFFu, idx, t);
            int s1 = __shfl_sync(0xFFFFFFFFu, idx, t + 1);
            int s2 = __shfl_sync(0xFFFFFFFFu, idx, t + 2);
            int s3 = __shfl_sync(0xFFFFFFFFu, idx, t + 3);
            uint2 v0 = ldcg2(d_xh + (size_t)s0 * CH + lane * 4);
            uint2 v1 = ldcg2(d_xh + (size_t)s1 * CH + lane * 4);
            uint2 v2 = ldcg2(d_xh + (size_t)s2 * CH + lane * 4);
            uint2 v3 = ldcg2(d_xh + (size_t)s3 * CH + lane * 4);
            acc_pair(acc, v0, v1);
            acc_pair(acc, v2, v3);
        }
        for (; t + 2 <= m; t += 2) {
            int s0 = __shfl_sync(0xFFFFFFFFu, idx, t);
            int s1 = __shfl_sync(0xFFFFFFFFu, idx, t + 1);
            uint2 v0 = ldcg2(d_xh + (size_t)s0 * CH + lane * 4);
            uint2 v1 = ldcg2(d_xh + (size_t)s1 * CH + lane * 4);
            acc_pair(acc, v0, v1);
        }
        for (; t < m; t++) {
            int s = __shfl_sync(0xFFFFFFFFu, idx, t);
            acc_h4(acc, ldcg2(d_xh + (size_t)s * CH + lane * 4));
        }
    }
    if (deg > CAP) {   // never taken on this input
        int oc = min(d_ovf_cnt, OVF_MAX);
        for (int o = 0; o < oc; o++) {
            if (d_ovf[2 * o + 1] == node) {
                int s = d_ovf[2 * o];
                acc_h4(acc, ldcg2(d_xh + (size_t)s * CH + lane * 4));
            }
        }
    }

    __half2 h01 = __floats2half2_rn(acc[0], acc[1]);
    __half2 h23 = __floats2half2_rn(acc[2], acc[3]);
    uint2 pack;
    pack.x = *(uint32_t*)&h01;
    pack.y = *(uint32_t*)&h23;
    *(uint2*)(d_sh + rb) = pack;
}

// ---------------------------------------------------------------------------
// Warp-MMA GEMM (row range [row_start, row_end)): R13 config unchanged.
// CTA M=64 x N=128 x K=128; 8 warps, warp tile 16x64; 4 CTAs/SM.
// ---------------------------------------------------------------------------
#define SA 0
#define SB (64 * LDA * 2)                 // 17408
#define SM_TOTAL (SB + 128 * LDA * 2)     // 52224

__global__ __launch_bounds__(256, 4)
void gemm_mma_kernel(const float* __restrict__ bias,
                     float* __restrict__ out,
                     int row_start, int row_end) {
    extern __shared__ char smem[];
    uint32_t sb = smem_to_u32(smem);
    int tid  = threadIdx.x;
    int wid  = tid >> 5;
    int lane = tid & 31;
    int row0 = row_start + blockIdx.x * 64;

    // ---- Copy A tile rows (fp16): 4 threads per row, 64 B each ----
    {
        int row = tid >> 2;              // 0..63
        int q   = tid & 3;               // quarter: 32 halfs = 64 B
        int rg  = row0 + row;
        size_t goff = (size_t)rg * CH + q * 32;
        size_t soff = ((size_t)row * LDA + q * 32) * 2;
        if (rg < row_end) {
            const uint4* ph = (const uint4*)(d_sh + goff);
            #pragma unroll
            for (int j = 0; j < 4; j++)
                *(uint4*)(smem + SA + soff + j * 16) = ph[j];
        } else {
            uint4 z = make_uint4(0, 0, 0, 0);
            #pragma unroll
            for (int j = 0; j < 4; j++)
                *(uint4*)(smem + SA + soff + j * 16) = z;
        }
    }
    // ---- Copy B tile (linear, 2176 uint4) ----
    {
        const uint4* sw = (const uint4*)d_Wh;
        uint4* dw = (uint4*)(smem + SB);
        #pragma unroll
        for (int i = 0; i < 9; i++) {
            int idx = tid + i * 256;
            if (idx < (128 * LDA * 2) / 16) dw[idx] = sw[idx];
        }
    }
    __syncthreads();

    // ---- Warp MMA mainloop: warp tile 16 rows x 64 cols ----
    int mw = (wid & 3) * 16;       // warp M offset (0..48)
    int nw = (wid >> 2) * 64;      // warp N offset (0 or 64)
    int lr = lane & 15;
    int lh = lane >> 4;

    float acc[8][4];
    #pragma unroll
    for (int t = 0; t < 8; t++)
        #pragma unroll
        for (int j = 0; j < 4; j++) acc[t][j] = 0.0f;

    #pragma unroll
    for (int kk = 0; kk < 8; kk++) {
        int k0 = kk * 16;
        uint32_t a[4], b[4][4];
        ldsm_x4(a, sb + SA + ((mw + lr) * LDA + k0 + lh * 8) * 2);
        #pragma unroll
        for (int nj = 0; nj < 4; nj++)
            ldsm_x4(b[nj], sb + SB + ((nw + nj * 16 + lr) * LDA + k0 + lh * 8) * 2);
        #pragma unroll
        for (int t = 0; t < 8; t++)
            mma_fp16(acc[t], a, b[t >> 1][t & 1], b[t >> 1][(t & 1) + 2]);
    }

    // ---- Epilogue: /(deg+1), +bias, relu ----
    int qr = lane >> 2;
    int qc = lane & 3;
    int ra  = row0 + mw + qr;
    int rb2 = ra + 8;
    bool va = ra < row_end, vb = rb2 < row_end;
    float inva = va ? 1.0f / (float)(d_deg[ra] + 1) : 0.0f;
    float invb = vb ? 1.0f / (float)(d_deg[rb2] + 1) : 0.0f;
    #pragma unroll
    for (int t = 0; t < 8; t++) {
        int col = nw + t * 8 + qc * 2;
        float2 bb = *(const float2*)(bias + col);
        if (va) {
            float2 o;
            o.x = fmaxf(fmaf(acc[t][0], inva, bb.x), 0.0f);
            o.y = fmaxf(fmaf(acc[t][1], inva, bb.y), 0.0f);
            *(float2*)(out + (size_t)ra * CH + col) = o;
        }
        if (vb) {
            float2 o;
            o.x = fmaxf(fmaf(acc[t][2], invb, bb.x), 0.0f);
            o.y = fmaxf(fmaf(acc[t][3], invb, bb.y), 0.0f);
            *(float2*)(out + (size_t)rb2 * CH + col) = o;
        }
    }
}

// ---------------------------------------------------------------------------
// kernel_launch — two-half pipeline:
//   main: prep, histo, gather(h0) -[ev1]-> gather(h1), gemm(h1), wait(ev2)
//   s1:   wait(ev1), gemm(h0) -[ev2]
// gemm(h0) (tensor/L1/smem) overlaps gather(h1) (L2, no smem).
// Inputs: x[f32 N*128], edge_index[2*E], weight[f32 128*128],
//         u[f32 128], c[f32 1], bias[f32 128]
// u, c are dead: HEADS==1 => softmax over one element == 1.
// ---------------------------------------------------------------------------
extern "C" void kernel_launch(void* const* d_in, const int* in_sizes, int n_in,
                              void* d_out, int out_size) {
    const float* x    = (const float*)d_in[0];
    const void*  ei   = d_in[1];
    const float* W    = (const float*)d_in[2];
    const float* bias = (const float*)d_in[5];
    float* out = (float*)d_out;

    int n_nodes = in_sizes[0] / CH;
    int n_edges = in_sizes[1] / 2;

    static cudaStream_t s1 = nullptr;
    static cudaEvent_t ev1 = nullptr, ev2 = nullptr;
    if (!s1) {
        cudaFuncSetAttribute(gemm_mma_kernel,
                             cudaFuncAttributeMaxDynamicSharedMemorySize,
                             SM_TOTAL);
        cudaStreamCreateWithFlags(&s1, cudaStreamNonBlocking);
        cudaEventCreateWithFlags(&ev1, cudaEventDisableTiming);
        cudaEventCreateWithFlags(&ev2, cudaEventDisableTiming);
    }

    // Half boundary aligned to the 64-row GEMM tile.
    int half = ((n_nodes / 2) + 63) & ~63;
    if (half > n_nodes) half = n_nodes;

    int prep_threads = n_nodes * (CH / 4);
    prep_kernel<<<(prep_threads + 255) / 256, 256>>>(x, W, ei, n_nodes);
    histo_fill_kernel<<<(n_edges + 255) / 256, 256>>>(ei, n_edges);

    // gather half 0
    int g0_warps = half;
    gather_kernel<<<(g0_warps * 32 + 127) / 128, 128>>>(0, half);
    cudaEventRecord(ev1, 0);

    // s1: gemm half 0 (overlaps gather half 1 on main stream)
    cudaStreamWaitEvent(s1, ev1, 0);
    gemm_mma_kernel<<<(half + 63) / 64, 256, SM_TOTAL, s1>>>(bias, out, 0, half);
    cudaEventRecord(ev2, s1);

    // main: gather half 1, then gemm half 1
    int g1_warps = n_nodes - half;
    if (g1_warps > 0) {
        gather_kernel<<<(g1_warps * 32 + 127) / 128, 128>>>(half, n_nodes);
        gemm_mma_kernel<<<(n_nodes - half + 63) / 64, 256, SM_TOTAL>>>(
            bias, out, half, n_nodes);
    }
    cudaStreamWaitEvent(0, ev2, 0);
}

// round 15
// speedup vs baseline: 1.0913x; 1.0913x over previous
#include <cuda_runtime.h>
#include <cuda_fp16.h>
#include <cstdint>

// Problem constants (fixed shapes for this instance)
#define N_NODES 50000
#define N_EDGES 600000
#define CH      128          // IN_CH == OUT_CH == 128, HEADS == 1
#define CAP     96           // per-node bucket capacity
#define OVF_MAX 16384        // overflow edge list capacity (correctness fallback)

#define LDA 136              // padded fp16 row stride (272 B) for ldmatrix tiles

// ---------------------------------------------------------------------------
// Scratch (no cudaMalloc allowed). All zero-initialized at module load;
// d_deg / d_ovf_cnt are re-zeroed by the GEMM epilogue each run, so every
// graph replay starts clean without a dedicated zero kernel.
// ---------------------------------------------------------------------------
__device__ __half d_xh[(size_t)N_NODES * CH];      // x in fp16
__device__ __half d_sh[(size_t)N_NODES * CH];      // aggregated features, fp16
__device__ int    d_deg[N_NODES];                  // in-degree (excl. self loop)
__device__ int    d_bucket[(size_t)N_NODES * CAP]; // per-dst source lists
__device__ int    d_ovf_cnt;
__device__ int    d_ovf[OVF_MAX * 2];
__device__ __half d_Wh[CH * LDA];                  // W^T [n][k], fp16, padded

// ---------------------------------------------------------------------------
// MMA helpers (baseline PTX, legal on plain sm_103)
// ---------------------------------------------------------------------------
__device__ __forceinline__ uint32_t smem_to_u32(const void* p) {
    uint32_t a;
    asm("{ .reg .u64 t; cvta.to.shared.u64 t, %1; cvt.u32.u64 %0, t; }"
        : "=r"(a) : "l"(p));
    return a;
}
__device__ __forceinline__ void ldsm_x4(uint32_t* r, uint32_t addr) {
    asm volatile("ldmatrix.sync.aligned.m8n8.x4.shared.b16 {%0,%1,%2,%3}, [%4];"
                 : "=r"(r[0]), "=r"(r[1]), "=r"(r[2]), "=r"(r[3]) : "r"(addr));
}
__device__ __forceinline__ void mma_fp16(float* c, const uint32_t* a,
                                         uint32_t b0, uint32_t b1) {
    asm volatile("mma.sync.aligned.m16n8k16.row.col.f32.f16.f16.f32 "
                 "{%0,%1,%2,%3}, {%4,%5,%6,%7}, {%8,%9}, {%0,%1,%2,%3};"
                 : "+f"(c[0]), "+f"(c[1]), "+f"(c[2]), "+f"(c[3])
                 : "r"(a[0]), "r"(a[1]), "r"(a[2]), "r"(a[3]), "r"(b0), "r"(b1));
}

// ---------------------------------------------------------------------------
// Fused kernel: blocks [0, histo_blocks) do histogram+bucket fill,
// blocks [histo_blocks, ...) convert x->fp16 and W->fp16 [n][k] padded.
// Histo blocks derive the edge-index dtype locally (16 broadcast u64 loads).
// d_deg starts zero (module init / previous run's gemm epilogue).
// ---------------------------------------------------------------------------
__global__ void fused_histo_conv_kernel(const float* __restrict__ x,
                                        const float* __restrict__ W,
                                        const void* __restrict__ ei,
                                        int n_nodes, int n_edges,
                                        int histo_blocks) {
    if ((int)blockIdx.x < histo_blocks) {
        // ---------------- histogram part ----------------
        __shared__ int s_is64;
        if (threadIdx.x == 0) {
            const unsigned long long* p = (const unsigned long long*)ei;
            int is64 = 1;
            #pragma unroll
            for (int j = 0; j < 16; j++)
                if (p[j] >> 32) is64 = 0;
            s_is64 = is64;
        }
        __syncthreads();

        int e = blockIdx.x * blockDim.x + threadIdx.x;
        if (e >= n_edges) return;
        int src, dst;
        if (s_is64) {
            const long long* p = (const long long*)ei;
            src = (int)p[e];
            dst = (int)p[n_edges + e];
        } else {
            const int* p = (const int*)ei;
            src = p[e];
            dst = p[n_edges + e];
        }
        int pos = atomicAdd(&d_deg[dst], 1);
        if (pos < CAP) {
            d_bucket[dst * CAP + pos] = src;
        } else {
            int j = atomicAdd(&d_ovf_cnt, 1);
            if (j < OVF_MAX) { d_ovf[2 * j] = src; d_ovf[2 * j + 1] = dst; }
        }
    } else {
        // ---------------- conversion part ----------------
        int i = (blockIdx.x - histo_blocks) * blockDim.x + threadIdx.x;
        int n4 = n_nodes * (CH / 4);
        if (i < n4) {
            float4 v = *(const float4*)(x + (size_t)i * 4);
            __half2 h01 = __floats2half2_rn(v.x, v.y);
            __half2 h23 = __floats2half2_rn(v.z, v.w);
            uint2 pack;
            pack.x = *(uint32_t*)&h01;
            pack.y = *(uint32_t*)&h23;
            *(uint2*)(d_xh + (size_t)i * 4) = pack;
        }
        if (i < CH * LDA) {
            int n = i / LDA;
            int k = i % LDA;
            float w = (k < CH) ? W[(size_t)k * CH + n] : 0.0f;
            d_Wh[i] = __float2half_rn(w);
        }
    }
}

// ---------------------------------------------------------------------------
// Gather: warp per node, fp16 rows, pairwise fp16 pre-add (__hadd2) then
// fp32 accumulate. (R13 internals, unchanged.)
// ---------------------------------------------------------------------------
__device__ __forceinline__ uint2 ldcg2(const __half* p) {
    uint2 v;
    asm volatile("ld.global.cg.v2.u32 {%0,%1}, [%2];"
                 : "=r"(v.x), "=r"(v.y) : "l"(p));
    return v;
}
__device__ __forceinline__ void acc_h4(float* f, uint2 v) {
    __half2 h01 = *(__half2*)&v.x;
    __half2 h23 = *(__half2*)&v.y;
    float2 f01 = __half22float2(h01);
    float2 f23 = __half22float2(h23);
    f[0] += f01.x; f[1] += f01.y; f[2] += f23.x; f[3] += f23.y;
}
__device__ __forceinline__ void acc_pair(float* f, uint2 va, uint2 vb) {
    __half2 p01 = __hadd2(*(__half2*)&va.x, *(__half2*)&vb.x);
    __half2 p23 = __hadd2(*(__half2*)&va.y, *(__half2*)&vb.y);
    float2 f01 = __half22float2(p01);
    float2 f23 = __half22float2(p23);
    f[0] += f01.x; f[1] += f01.y; f[2] += f23.x; f[3] += f23.y;
}

__global__ __launch_bounds__(128)
void gather_kernel(int n_nodes) {
    int node = (blockIdx.x * blockDim.x + threadIdx.x) >> 5;
    int lane = threadIdx.x & 31;
    if (node >= n_nodes) return;

    int deg = d_deg[node];
    int nb  = min(deg, CAP);
    const size_t rb = (size_t)node * CH + lane * 4;

    float acc[4] = {0.f, 0.f, 0.f, 0.f};
    acc_h4(acc, ldcg2(d_xh + rb));                 // self loop

    int base = node * CAP;
    for (int e0 = 0; e0 < nb; e0 += 32) {
        int idx = 0;
        if (e0 + lane < nb) idx = d_bucket[base + e0 + lane];
        int m = min(32, nb - e0);
        int t = 0;
        for (; t + 4 <= m; t += 4) {
            int s0 = __shfl_sync(0xFFFFFFFFu, idx, t);
            int s1 = __shfl_sync(0xFFFFFFFFu, idx, t + 1);
            int s2 = __shfl_sync(0xFFFFFFFFu, idx, t + 2);
            int s3 = __shfl_sync(0xFFFFFFFFu, idx, t + 3);
            uint2 v0 = ldcg2(d_xh + (size_t)s0 * CH + lane * 4);
            uint2 v1 = ldcg2(d_xh + (size_t)s1 * CH + lane * 4);
            uint2 v2 = ldcg2(d_xh + (size_t)s2 * CH + lane * 4);
            uint2 v3 = ldcg2(d_xh + (size_t)s3 * CH + lane * 4);
            acc_pair(acc, v0, v1);
            acc_pair(acc, v2, v3);
        }
        for (; t + 2 <= m; t += 2) {
            int s0 = __shfl_sync(0xFFFFFFFFu, idx, t);
            int s1 = __shfl_sync(0xFFFFFFFFu, idx, t + 1);
            uint2 v0 = ldcg2(d_xh + (size_t)s0 * CH + lane * 4);
            uint2 v1 = ldcg2(d_xh + (size_t)s1 * CH + lane * 4);
            acc_pair(acc, v0, v1);
        }
        for (; t < m; t++) {
            int s = __shfl_sync(0xFFFFFFFFu, idx, t);
            acc_h4(acc, ldcg2(d_xh + (size_t)s * CH + lane * 4));
        }
    }
    if (deg > CAP) {   // never taken on this input
        int oc = min(d_ovf_cnt, OVF_MAX);
        for (int o = 0; o < oc; o++) {
            if (d_ovf[2 * o + 1] == node) {
                int s = d_ovf[2 * o];
                acc_h4(acc, ldcg2(d_xh + (size_t)s * CH + lane * 4));
            }
        }
    }

    __half2 h01 = __floats2half2_rn(acc[0], acc[1]);
    __half2 h23 = __floats2half2_rn(acc[2], acc[3]);
    uint2 pack;
    pack.x = *(uint32_t*)&h01;
    pack.y = *(uint32_t*)&h23;
    *(uint2*)(d_sh + rb) = pack;
}

// ---------------------------------------------------------------------------
// Warp-MMA GEMM (R13 config): out = relu((s@W)/(deg+1) + bias)
// CTA M=64 x N=128 x K=128; 8 warps, warp tile 16x64; 4 CTAs/SM.
// Epilogue additionally RE-ZEROES d_deg for its rows (after all reads,
// behind a __syncthreads) and resets d_ovf_cnt, so the next run starts clean.
// ---------------------------------------------------------------------------
#define SA 0
#define SB (64 * LDA * 2)                 // 17408
#define SM_TOTAL (SB + 128 * LDA * 2)     // 52224

__global__ __launch_bounds__(256, 4)
void gemm_mma_kernel(const float* __restrict__ bias,
                     float* __restrict__ out,
                     int n_nodes) {
    extern __shared__ char smem[];
    uint32_t sb = smem_to_u32(smem);
    int tid  = threadIdx.x;
    int wid  = tid >> 5;
    int lane = tid & 31;
    int row0 = blockIdx.x * 64;

    // ---- Copy A tile rows (fp16): 4 threads per row, 64 B each ----
    {
        int row = tid >> 2;              // 0..63
        int q   = tid & 3;               // quarter: 32 halfs = 64 B
        int rg  = row0 + row;
        size_t goff = (size_t)rg * CH + q * 32;
        size_t soff = ((size_t)row * LDA + q * 32) * 2;
        if (rg < n_nodes) {
            const uint4* ph = (const uint4*)(d_sh + goff);
            #pragma unroll
            for (int j = 0; j < 4; j++)
                *(uint4*)(smem + SA + soff + j * 16) = ph[j];
        } else {
            uint4 z = make_uint4(0, 0, 0, 0);
            #pragma unroll
            for (int j = 0; j < 4; j++)
                *(uint4*)(smem + SA + soff + j * 16) = z;
        }
    }
    // ---- Copy B tile (linear, 2176 uint4) ----
    {
        const uint4* sw = (const uint4*)d_Wh;
        uint4* dw = (uint4*)(smem + SB);
        #pragma unroll
        for (int i = 0; i < 9; i++) {
            int idx = tid + i * 256;
            if (idx < (128 * LDA * 2) / 16) dw[idx] = sw[idx];
        }
    }
    __syncthreads();

    // ---- Warp MMA mainloop: warp tile 16 rows x 64 cols ----
    int mw = (wid & 3) * 16;       // warp M offset (0..48)
    int nw = (wid >> 2) * 64;      // warp N offset (0 or 64)
    int lr = lane & 15;
    int lh = lane >> 4;

    float acc[8][4];
    #pragma unroll
    for (int t = 0; t < 8; t++)
        #pragma unroll
        for (int j = 0; j < 4; j++) acc[t][j] = 0.0f;

    #pragma unroll
    for (int kk = 0; kk < 8; kk++) {
        int k0 = kk * 16;
        uint32_t a[4], b[4][4];
        ldsm_x4(a, sb + SA + ((mw + lr) * LDA + k0 + lh * 8) * 2);
        #pragma unroll
        for (int nj = 0; nj < 4; nj++)
            ldsm_x4(b[nj], sb + SB + ((nw + nj * 16 + lr) * LDA + k0 + lh * 8) * 2);
        #pragma unroll
        for (int t = 0; t < 8; t++)
            mma_fp16(acc[t], a, b[t >> 1][t & 1], b[t >> 1][(t & 1) + 2]);
    }

    // ---- Epilogue: /(deg+1), +bias, relu; then re-zero deg for next run ----
    int qr = lane >> 2;
    int qc = lane & 3;
    int ra  = row0 + mw + qr;
    int rb2 = ra + 8;
    bool va = ra < n_nodes, vb = rb2 < n_nodes;
    float inva = va ? 1.0f / (float)(d_deg[ra] + 1) : 0.0f;
    float invb = vb ? 1.0f / (float)(d_deg[rb2] + 1) : 0.0f;

    // All deg reads for this CTA's rows complete before any thread zeroes.
    __syncthreads();
    if ((wid >> 2) == 0 && qc == 0) {   // one writer per row
        if (va) d_deg[ra] = 0;
        if (vb) d_deg[rb2] = 0;
    }
    if (blockIdx.x == 0 && tid == 0) d_ovf_cnt = 0;

    #pragma unroll
    for (int t = 0; t < 8; t++) {
        int col = nw + t * 8 + qc * 2;
        float2 bb = *(const float2*)(bias + col);
        if (va) {
            float2 o;
            o.x = fmaxf(fmaf(acc[t][0], inva, bb.x), 0.0f);
            o.y = fmaxf(fmaf(acc[t][1], inva, bb.y), 0.0f);
            *(float2*)(out + (size_t)ra * CH + col) = o;
        }
        if (vb) {
            float2 o;
            o.x = fmaxf(fmaf(acc[t][2], invb, bb.x), 0.0f);
            o.y = fmaxf(fmaf(acc[t][3], invb, bb.y), 0.0f);
            *(float2*)(out + (size_t)rb2 * CH + col) = o;
        }
    }
}

// ---------------------------------------------------------------------------
// kernel_launch — 3 launches: fused(histo || conv) -> gather -> gemm.
// Inputs: x[f32 N*128], edge_index[2*E], weight[f32 128*128],
//         u[f32 128], c[f32 1], bias[f32 128]
// u, c are dead: HEADS==1 => softmax over one element == 1.
// ---------------------------------------------------------------------------
extern "C" void kernel_launch(void* const* d_in, const int* in_sizes, int n_in,
                              void* d_out, int out_size) {
    const float* x    = (const float*)d_in[0];
    const void*  ei   = d_in[1];
    const float* W    = (const float*)d_in[2];
    const float* bias = (const float*)d_in[5];
    float* out = (float*)d_out;

    int n_nodes = in_sizes[0] / CH;
    int n_edges = in_sizes[1] / 2;

    static bool attr_set = false;
    if (!attr_set) {
        cudaFuncSetAttribute(gemm_mma_kernel,
                             cudaFuncAttributeMaxDynamicSharedMemorySize,
                             SM_TOTAL);
        attr_set = true;
    }

    int histo_blocks = (n_edges + 255) / 256;
    int conv_items   = n_nodes * (CH / 4);            // >= CH*LDA
    int conv_blocks  = (conv_items + 255) / 256;
    fused_histo_conv_kernel<<<histo_blocks + conv_blocks, 256>>>(
        x, W, ei, n_nodes, n_edges, histo_blocks);

    gather_kernel<<<(n_nodes * 32 + 127) / 128, 128>>>(n_nodes);
    gemm_mma_kernel<<<(n_nodes + 63) / 64, 256, SM_TOTAL>>>(bias, out, n_nodes);
}